// round 1
// baseline (speedup 1.0000x reference)
#include <cuda_runtime.h>
#include <cstdint>
#include <math.h>

// ---------------------------------------------------------------------------
// QLayer_Block: fully int8-exact implementation.
// All GEMM operands are fake-quantized (value = scale * int8), so each GEMM is
// computed exactly with mma.sync.m16n8k32.s8 tensor cores; epilogues apply the
// float scales, biases, fq() requantization, GELU, layer-scale and residuals.
// ---------------------------------------------------------------------------

namespace {

constexpr int BATCH = 128;
constexpr int NTOK  = 196;
constexpr int DIM   = 768;
constexpr int HID   = 3072;
constexpr int RNK   = 384;
constexpr long TROWS = (long)BATCH * NTOK;   // 25088

// ---- device scratch (no allocations allowed) ----
__device__ __align__(256) int8_t g_qWattn[NTOK * NTOK];
__device__ __align__(256) int8_t g_qW1vt[RNK * DIM];
__device__ __align__(256) int8_t g_qW1u [HID * RNK];
__device__ __align__(256) int8_t g_qW2vt[RNK * HID];
__device__ __align__(256) int8_t g_qW2u [DIM * RNK];

__device__ __align__(256) float g_v1a[DIM];   // fq_w(norm1_a)
__device__ __align__(256) float g_v2a[DIM];   // fq_w(norm2_a)
__device__ __align__(256) float g_g1 [DIM];   // fq_w(gamma1)
__device__ __align__(256) float g_g2 [DIM];   // fq_w(gamma2)
__device__ float g_absmax[8];                 // slots 0..4 used

__device__ __align__(256) int8_t g_qa1t[(long)BATCH * DIM * NTOK]; // [b][d][n]
__device__ __align__(256) int8_t g_qx1 [TROWS * DIM];              // x1 / s8
__device__ __align__(256) int8_t g_qa2 [TROWS * DIM];              // norm2 act
__device__ __align__(256) int8_t g_qa3 [TROWS * RNK];
__device__ __align__(256) int8_t g_qa4 [TROWS * HID];
__device__ __align__(256) int8_t g_qa5 [TROWS * RNK];

__device__ __forceinline__ float fqq(float x, float s) {
    // clip(round(x/s), -128, 127); round = rint (half-to-even, matches jnp.round)
    float r = rintf(__fdiv_rn(x, s));
    return fminf(127.f, fmaxf(-128.f, r));
}

__device__ __forceinline__ float wscale(int slot) {
    return __fadd_rn(__fdiv_rn(g_absmax[slot], 127.f), 1e-8f);
}

// ---------------------------------------------------------------------------
// small prep kernels
// ---------------------------------------------------------------------------

__global__ void quant_vectors_k(const float* __restrict__ n1a,
                                const float* __restrict__ n2a,
                                const float* __restrict__ g1,
                                const float* __restrict__ g2) {
    __shared__ float red[256];
    int v = blockIdx.x;
    const float* src = (v == 0) ? n1a : (v == 1) ? n2a : (v == 2) ? g1 : g2;
    float* dst = (v == 0) ? g_v1a : (v == 1) ? g_v2a : (v == 2) ? g_g1 : g_g2;
    int tid = threadIdx.x;
    if (v == 0 && tid < 8) g_absmax[tid] = 0.f;   // reset before absmax kernels
    float m = 0.f;
    for (int i = tid; i < DIM; i += 256) m = fmaxf(m, fabsf(src[i]));
    red[tid] = m;
    __syncthreads();
    for (int s = 128; s > 0; s >>= 1) {
        if (tid < s) red[tid] = fmaxf(red[tid], red[tid + s]);
        __syncthreads();
    }
    float sc = __fadd_rn(__fdiv_rn(red[0], 127.f), 1e-8f);
    for (int i = tid; i < DIM; i += 256)
        dst[i] = __fmul_rn(sc, fqq(src[i], sc));
}

__global__ void absmax_k(const float* __restrict__ w, int n, int slot) {
    float m = 0.f;
    for (int i = blockIdx.x * blockDim.x + threadIdx.x; i < n;
         i += gridDim.x * blockDim.x)
        m = fmaxf(m, fabsf(w[i]));
#pragma unroll
    for (int o = 16; o; o >>= 1) m = fmaxf(m, __shfl_xor_sync(0xffffffffu, m, o));
    if ((threadIdx.x & 31) == 0)
        atomicMax((int*)&g_absmax[slot], __float_as_int(m)); // positives only
}

__global__ void quantw_k(const float* __restrict__ w, int n, int slot) {
    int8_t* dst = (slot == 0) ? g_qWattn : (slot == 1) ? g_qW1vt :
                  (slot == 2) ? g_qW1u   : (slot == 3) ? g_qW2vt : g_qW2u;
    float s = wscale(slot);
    for (int i = blockIdx.x * blockDim.x + threadIdx.x; i < n;
         i += gridDim.x * blockDim.x)
        dst[i] = (int8_t)fqq(w[i], s);
}

// stage 0: qa1t[b][d][n] = fq(x[b,n,d]*fqw(norm1_a)[d] + norm1_b[d], s0) / s0
__global__ void stage0_k(const float* __restrict__ x,
                         const float* __restrict__ nb1,
                         const float* __restrict__ sc) {
    __shared__ float tile[32][33];
    int d0 = blockIdx.x * 32, n0 = blockIdx.y * 32, b = blockIdx.z;
    float s0 = sc[0];
    int tx = threadIdx.x, ty = threadIdx.y;
#pragma unroll
    for (int r = 0; r < 4; ++r) {
        int n = n0 + ty + r * 8, d = d0 + tx;
        float v = 0.f;
        if (n < NTOK) v = x[((long)b * NTOK + n) * DIM + d];
        tile[ty + r * 8][tx] = v;   // [n_local][d_local]
    }
    __syncthreads();
#pragma unroll
    for (int r = 0; r < 4; ++r) {
        int d = d0 + ty + r * 8, n = n0 + tx;
        if (n < NTOK) {
            float v = __fadd_rn(__fmul_rn(tile[tx][ty + r * 8], g_v1a[d]), nb1[d]);
            g_qa1t[((long)b * DIM + d) * NTOK + n] = (int8_t)fqq(v, s0);
        }
    }
}

// ---------------------------------------------------------------------------
// int8 tensor-core GEMM with fused per-stage epilogues
// C[M,N] = A[M,K] (k-major) * B[N,K]^T (k-major), s32 accumulate
// Stages: 0=attn(batched), 1=fc1_vt, 2=fc1_u, 3=fc2_vt, 4=fc2_u
// ---------------------------------------------------------------------------

__device__ __forceinline__ void mma_s8(int* c, const unsigned* a,
                                       unsigned b0, unsigned b1) {
    asm volatile(
        "mma.sync.aligned.m16n8k32.row.col.s32.s8.s8.s32 "
        "{%0,%1,%2,%3},{%4,%5,%6,%7},{%8,%9},{%0,%1,%2,%3};\n"
        : "+r"(c[0]), "+r"(c[1]), "+r"(c[2]), "+r"(c[3])
        : "r"(a[0]), "r"(a[1]), "r"(a[2]), "r"(a[3]), "r"(b0), "r"(b1));
}

template <int STAGE>
__global__ void __launch_bounds__(256)
gemm_s8_k(int M, int N, int K,
          const float* __restrict__ sc,
          const float* __restrict__ bias,
          const float* __restrict__ xorg,   // stage 0 only: original x
          const float* __restrict__ nb2,    // stage 0 only: norm2_b
          float* __restrict__ outf) {       // stage 4 only

    constexpr int AST = 80;                 // padded smem row stride (bytes)
    __shared__ int8_t smA[2][128 * AST];
    __shared__ int8_t smB[2][128 * AST];

    const int tid  = threadIdx.x;
    const int warp = tid >> 5, lane = tid & 31;
    const int wm = warp >> 2, wn = warp & 3;          // 2 x 4 warp grid
    const int m0 = blockIdx.y * 128;
    const int n0 = blockIdx.x * 128;
    const int bz = blockIdx.z;

    const int8_t* Ab;
    const int8_t* Bb;
    if (STAGE == 0)      { Ab = g_qWattn; Bb = g_qa1t + (long)bz * DIM * NTOK; }
    else if (STAGE == 1) { Ab = g_qa2;    Bb = g_qW1vt; }
    else if (STAGE == 2) { Ab = g_qa3;    Bb = g_qW1u; }
    else if (STAGE == 3) { Ab = g_qa4;    Bb = g_qW2vt; }
    else                 { Ab = g_qa5;    Bb = g_qW2u; }

    int acc[4][4][4];
#pragma unroll
    for (int i = 0; i < 4; ++i)
#pragma unroll
        for (int j = 0; j < 4; ++j)
#pragma unroll
            for (int t = 0; t < 4; ++t) acc[i][j][t] = 0;

    const int row = tid >> 2;           // 0..63
    const int ch4 = (tid & 3) * 16;     // 16B chunk offset in K

    auto ldrow = [&](const int8_t* base, int grow, int rmax, int gk) -> int4 {
        int4 v = make_int4(0, 0, 0, 0);
        if (STAGE == 0) {               // K = 196 (4B-aligned only)
            if (grow < rmax) {
                const int8_t* p = base + (long)grow * K + gk;
                int* vp = (int*)&v;
#pragma unroll
                for (int w = 0; w < 4; ++w) {
                    int kk = gk + w * 4;
                    if (kk + 4 <= K) vp[w] = *(const int*)(p + w * 4);
                }
            }
        } else {                        // K multiple of 16, 16B aligned
            if (grow < rmax && gk < K)
                v = *(const int4*)(base + (long)grow * K + gk);
        }
        return v;
    };

    const int ktiles = (K + 63) >> 6;
    int4 ra0 = ldrow(Ab, m0 + row,      M, ch4);
    int4 ra1 = ldrow(Ab, m0 + row + 64, M, ch4);
    int4 rb0 = ldrow(Bb, n0 + row,      N, ch4);
    int4 rb1 = ldrow(Bb, n0 + row + 64, N, ch4);

    int buf = 0;
    for (int kt = 0; kt < ktiles; ++kt) {
        *(int4*)&smA[buf][row * AST + ch4]        = ra0;
        *(int4*)&smA[buf][(row + 64) * AST + ch4] = ra1;
        *(int4*)&smB[buf][row * AST + ch4]        = rb0;
        *(int4*)&smB[buf][(row + 64) * AST + ch4] = rb1;
        __syncthreads();

        if (kt + 1 < ktiles) {
            int gk = (kt + 1) * 64 + ch4;
            ra0 = ldrow(Ab, m0 + row,      M, gk);
            ra1 = ldrow(Ab, m0 + row + 64, M, gk);
            rb0 = ldrow(Bb, n0 + row,      N, gk);
            rb1 = ldrow(Bb, n0 + row + 64, N, gk);
        }

#pragma unroll
        for (int ks = 0; ks < 2; ++ks) {
            unsigned af[4][4];
#pragma unroll
            for (int i = 0; i < 4; ++i) {
                const int8_t* p = &smA[buf][(wm * 64 + i * 16 + (lane >> 2)) * AST
                                            + ks * 32 + (lane & 3) * 4];
                af[i][0] = *(const unsigned*)p;
                af[i][1] = *(const unsigned*)(p + 8 * AST);
                af[i][2] = *(const unsigned*)(p + 16);
                af[i][3] = *(const unsigned*)(p + 8 * AST + 16);
            }
#pragma unroll
            for (int j = 0; j < 4; ++j) {
                const int8_t* q = &smB[buf][(wn * 32 + j * 8 + (lane >> 2)) * AST
                                            + ks * 32 + (lane & 3) * 4];
                unsigned b0 = *(const unsigned*)q;
                unsigned b1 = *(const unsigned*)(q + 16);
#pragma unroll
                for (int i = 0; i < 4; ++i) mma_s8(acc[i][j], af[i], b0, b1);
            }
        }
        buf ^= 1;
        __syncthreads();
    }

    // ---- epilogue ----
    const float sc1 = sc[1], sc2 = sc[2], sc3 = sc[3], sc4 = sc[4];
    const float sc5 = sc[5], sc6 = sc[6], sc7 = sc[7], sc8 = sc[8], sc9 = sc[9];
    float swp;
    if (STAGE == 0)      swp = sc[0] * wscale(0);
    else if (STAGE == 1) swp = sc2 * wscale(1);
    else if (STAGE == 2) swp = sc4 * wscale(2);
    else if (STAGE == 3) swp = sc6 * wscale(3);
    else                 swp = sc7 * wscale(4);

#pragma unroll
    for (int i = 0; i < 4; ++i) {
        int mbase = m0 + wm * 64 + i * 16 + (lane >> 2);
#pragma unroll
        for (int j = 0; j < 4; ++j) {
            int nbase = n0 + wn * 32 + j * 8 + ((lane & 3) << 1);
#pragma unroll
            for (int t = 0; t < 4; ++t) {
                int mm = mbase + ((t & 2) ? 8 : 0);
                int nn = nbase + (t & 1);
                if (mm >= M || nn >= N) continue;
                float a = (float)acc[i][j][t];

                if (STAGE == 0) {
                    // + attn_b[m]; fq(s1); *gamma1; +x; fq(s8) -> qx1
                    // then norm2 affine; fq(s2) -> qa2
                    float val = __fadd_rn(__fmul_rn(a, swp), bias[mm]);
                    float q1  = fqq(val, sc1);
                    float tv  = __fmul_rn(__fmul_rn(sc1, q1), g_g1[nn]);
                    long idx  = ((long)bz * NTOK + mm) * DIM + nn;
                    float x1  = __fadd_rn(tv, xorg[idx]);
                    float q8  = fqq(x1, sc8);
                    g_qx1[idx] = (int8_t)q8;
                    float x1v = __fmul_rn(sc8, q8);
                    float h   = __fadd_rn(__fmul_rn(x1v, g_v2a[nn]), nb2[nn]);
                    g_qa2[idx] = (int8_t)fqq(h, sc2);
                } else if (STAGE == 1) {
                    float val = __fadd_rn(__fmul_rn(a, swp), bias[nn]);
                    g_qa3[(long)mm * RNK + nn] = (int8_t)fqq(val, sc4);
                } else if (STAGE == 2) {
                    float val = __fadd_rn(__fmul_rn(a, swp), bias[nn]);
                    float tq  = __fmul_rn(sc5, fqq(val, sc5));
                    float ge  = __fmul_rn(__fmul_rn(0.5f, tq),
                                __fadd_rn(1.f, erff(__fmul_rn(tq, 0.70710678118654752f))));
                    g_qa4[(long)mm * HID + nn] = (int8_t)fqq(ge, sc6);
                } else if (STAGE == 3) {
                    float val = __fadd_rn(__fmul_rn(a, swp), bias[nn]);
                    g_qa5[(long)mm * RNK + nn] = (int8_t)fqq(val, sc7);
                } else {
                    float val = __fadd_rn(__fmul_rn(a, swp), bias[nn]);
                    float v   = __fmul_rn(__fmul_rn(sc3, fqq(val, sc3)), g_g2[nn]);
                    long idx  = (long)mm * DIM + nn;
                    float x1v = __fmul_rn(sc8, (float)g_qx1[idx]);
                    outf[idx] = __fmul_rn(sc9, fqq(__fadd_rn(v, x1v), sc9));
                }
            }
        }
    }
}

} // anonymous namespace

// ---------------------------------------------------------------------------
extern "C" void kernel_launch(void* const* d_in, const int* in_sizes, int n_in,
                              void* d_out, int out_size) {
    const float* x    = (const float*)d_in[0];
    const float* n1a  = (const float*)d_in[1];
    const float* n1b  = (const float*)d_in[2];
    const float* attw = (const float*)d_in[3];
    const float* attb = (const float*)d_in[4];
    const float* g1   = (const float*)d_in[5];
    const float* n2a  = (const float*)d_in[6];
    const float* n2b  = (const float*)d_in[7];
    const float* w1vt = (const float*)d_in[8];
    const float* b1vt = (const float*)d_in[9];
    const float* w1u  = (const float*)d_in[10];
    const float* b1u  = (const float*)d_in[11];
    const float* w2vt = (const float*)d_in[12];
    const float* b2vt = (const float*)d_in[13];
    const float* w2u  = (const float*)d_in[14];
    const float* b2u  = (const float*)d_in[15];
    const float* g2   = (const float*)d_in[16];
    const float* sc   = (const float*)d_in[17];
    float* out = (float*)d_out;

    // weight prep (also zeroes g_absmax before the atomics)
    quant_vectors_k<<<4, 256>>>(n1a, n2a, g1, g2);

    absmax_k<<<256, 256>>>(attw, NTOK * NTOK, 0);
    absmax_k<<<256, 256>>>(w1vt, RNK * DIM,   1);
    absmax_k<<<256, 256>>>(w1u,  HID * RNK,   2);
    absmax_k<<<256, 256>>>(w2vt, RNK * HID,   3);
    absmax_k<<<256, 256>>>(w2u,  DIM * RNK,   4);

    quantw_k<<<256, 256>>>(attw, NTOK * NTOK, 0);
    quantw_k<<<256, 256>>>(w1vt, RNK * DIM,   1);
    quantw_k<<<256, 256>>>(w1u,  HID * RNK,   2);
    quantw_k<<<256, 256>>>(w2vt, RNK * HID,   3);
    quantw_k<<<256, 256>>>(w2u,  DIM * RNK,   4);

    // stage 0: norm1 + fq(s0), transposed to [b][d][n]
    {
        dim3 grid(DIM / 32, (NTOK + 31) / 32, BATCH);
        dim3 blk(32, 8);
        stage0_k<<<grid, blk>>>(x, n1b, sc);
    }

    // attn token-mixing GEMM (batched over z) + fused residual/norm2 epilogue
    {
        dim3 grid(DIM / 128, (NTOK + 127) / 128, BATCH);
        gemm_s8_k<0><<<grid, 256>>>(NTOK, DIM, NTOK, sc, attb, x, n2b, nullptr);
    }
    // fc1_vt: [T,768] x [384,768]^T
    {
        dim3 grid(RNK / 128, (int)(TROWS / 128), 1);
        gemm_s8_k<1><<<grid, 256>>>((int)TROWS, RNK, DIM, sc, b1vt, x, n2b, nullptr);
    }
    // fc1_u: [T,384] x [3072,384]^T  (+ GELU)
    {
        dim3 grid(HID / 128, (int)(TROWS / 128), 1);
        gemm_s8_k<2><<<grid, 256>>>((int)TROWS, HID, RNK, sc, b1u, x, n2b, nullptr);
    }
    // fc2_vt: [T,3072] x [384,3072]^T
    {
        dim3 grid(RNK / 128, (int)(TROWS / 128), 1);
        gemm_s8_k<3><<<grid, 256>>>((int)TROWS, RNK, HID, sc, b2vt, x, n2b, nullptr);
    }
    // fc2_u: [T,384] x [768,384]^T + gamma2 + residual -> out
    {
        dim3 grid(DIM / 128, (int)(TROWS / 128), 1);
        gemm_s8_k<4><<<grid, 256>>>((int)TROWS, DIM, RNK, sc, b2u, x, n2b, out);
    }
}

// round 2
// speedup vs baseline: 1.0889x; 1.0889x over previous
#include <cuda_runtime.h>
#include <cstdint>
#include <math.h>

// ---------------------------------------------------------------------------
// QLayer_Block: int8-exact implementation, round 2.
// All GEMM operands are fake-quantized (value = scale * int8), so each GEMM is
// computed exactly with mma.sync.m16n8k32.s8 tensor cores. This round adds
// cp.async double-buffered pipelines, ldmatrix fragment loads, zero-padded
// attn K (256) for fully unpredicated 16B loads, and fused prep kernels.
// ---------------------------------------------------------------------------

namespace {

constexpr int BATCH = 128;
constexpr int NTOK  = 196;
constexpr int DIM   = 768;
constexpr int HID   = 3072;
constexpr int RNK   = 384;
constexpr int KPAD  = 256;                    // attn contraction dim, padded
constexpr long TROWS = (long)BATCH * NTOK;    // 25088 (multiple of 128)

// ---- device scratch (no allocations allowed) ----
__device__ __align__(256) int8_t g_qWattn[256 * KPAD];   // zero-padded
__device__ __align__(256) int8_t g_qW1vt[RNK * DIM];
__device__ __align__(256) int8_t g_qW1u [HID * RNK];
__device__ __align__(256) int8_t g_qW2vt[RNK * HID];
__device__ __align__(256) int8_t g_qW2u [DIM * RNK];

__device__ __align__(256) float g_v1a[DIM];   // fq_w(norm1_a)
__device__ __align__(256) float g_v2a[DIM];   // fq_w(norm2_a)
__device__ __align__(256) float g_g1 [DIM];   // fq_w(gamma1)
__device__ __align__(256) float g_g2 [DIM];   // fq_w(gamma2)
__device__ float g_absmax[8];

__device__ __align__(256) int8_t g_qa1t[(long)BATCH * DIM * KPAD]; // [b][d][npad]
__device__ __align__(256) int8_t g_qx1 [TROWS * DIM];
__device__ __align__(256) int8_t g_qa2 [TROWS * DIM];
__device__ __align__(256) int8_t g_qa3 [TROWS * RNK];
__device__ __align__(256) int8_t g_qa4 [TROWS * HID];
__device__ __align__(256) int8_t g_qa5 [TROWS * RNK];

__device__ __forceinline__ float fqq(float x, float s) {
    float r = rintf(__fdiv_rn(x, s));     // rint == jnp.round (half-to-even)
    return fminf(127.f, fmaxf(-128.f, r));
}

__device__ __forceinline__ float wscale(int slot) {
    return __fadd_rn(__fdiv_rn(g_absmax[slot], 127.f), 1e-8f);
}

// ---------------------------------------------------------------------------
// prep kernels
// ---------------------------------------------------------------------------

__global__ void quant_vectors_k(const float* __restrict__ n1a,
                                const float* __restrict__ n2a,
                                const float* __restrict__ g1,
                                const float* __restrict__ g2) {
    __shared__ float red[256];
    int v = blockIdx.x;
    const float* src = (v == 0) ? n1a : (v == 1) ? n2a : (v == 2) ? g1 : g2;
    float* dst = (v == 0) ? g_v1a : (v == 1) ? g_v2a : (v == 2) ? g_g1 : g_g2;
    int tid = threadIdx.x;
    if (v == 0 && tid < 8) g_absmax[tid] = 0.f;
    float m = 0.f;
    for (int i = tid; i < DIM; i += 256) m = fmaxf(m, fabsf(src[i]));
    red[tid] = m;
    __syncthreads();
    for (int s = 128; s > 0; s >>= 1) {
        if (tid < s) red[tid] = fmaxf(red[tid], red[tid + s]);
        __syncthreads();
    }
    float sc = __fadd_rn(__fdiv_rn(red[0], 127.f), 1e-8f);
    for (int i = tid; i < DIM; i += 256)
        dst[i] = __fmul_rn(sc, fqq(src[i], sc));
}

__global__ void absmax_all_k(const float* __restrict__ w0, const float* __restrict__ w1,
                             const float* __restrict__ w2, const float* __restrict__ w3,
                             const float* __restrict__ w4) {
    int seg = blockIdx.y;
    const float* w; int n;
    if (seg == 0)      { w = w0; n = NTOK * NTOK; }
    else if (seg == 1) { w = w1; n = RNK * DIM; }
    else if (seg == 2) { w = w2; n = HID * RNK; }
    else if (seg == 3) { w = w3; n = RNK * HID; }
    else               { w = w4; n = DIM * RNK; }
    float m = 0.f;
    for (int i = blockIdx.x * blockDim.x + threadIdx.x; i < n;
         i += gridDim.x * blockDim.x)
        m = fmaxf(m, fabsf(w[i]));
#pragma unroll
    for (int o = 16; o; o >>= 1) m = fmaxf(m, __shfl_xor_sync(0xffffffffu, m, o));
    if ((threadIdx.x & 31) == 0)
        atomicMax((int*)&g_absmax[seg], __float_as_int(m));
}

__global__ void quantw_all_k(const float* __restrict__ w0, const float* __restrict__ w1,
                             const float* __restrict__ w2, const float* __restrict__ w3,
                             const float* __restrict__ w4) {
    int seg = blockIdx.y;
    float s = wscale(seg);
    if (seg == 0) {
        // attn weights into zero-padded [256][KPAD]
        for (int i = blockIdx.x * blockDim.x + threadIdx.x; i < 256 * KPAD;
             i += gridDim.x * blockDim.x) {
            int m = i >> 8, k = i & (KPAD - 1);
            int8_t v = 0;
            if (m < NTOK && k < NTOK) v = (int8_t)fqq(w0[m * NTOK + k], s);
            g_qWattn[i] = v;
        }
        return;
    }
    const float* w; int8_t* dst; int n;
    if (seg == 1)      { w = w1; dst = g_qW1vt; n = RNK * DIM; }
    else if (seg == 2) { w = w2; dst = g_qW1u;  n = HID * RNK; }
    else if (seg == 3) { w = w3; dst = g_qW2vt; n = RNK * HID; }
    else               { w = w4; dst = g_qW2u;  n = DIM * RNK; }
    for (int i = blockIdx.x * blockDim.x + threadIdx.x; i < n;
         i += gridDim.x * blockDim.x)
        dst[i] = (int8_t)fqq(w[i], s);
}

// stage 0: qa1t[b][d][n] = fq(x[b,n,d]*fqw(norm1_a)[d] + norm1_b[d], s0)/s0, pad 0
__global__ void stage0_k(const float* __restrict__ x,
                         const float* __restrict__ nb1,
                         const float* __restrict__ sc) {
    __shared__ float tile[32][33];
    int d0 = blockIdx.x * 32, n0 = blockIdx.y * 32, b = blockIdx.z;
    float s0 = sc[0];
    int tx = threadIdx.x, ty = threadIdx.y;
#pragma unroll
    for (int r = 0; r < 4; ++r) {
        int n = n0 + ty + r * 8, d = d0 + tx;
        float v = 0.f;
        if (n < NTOK) v = x[((long)b * NTOK + n) * DIM + d];
        tile[ty + r * 8][tx] = v;
    }
    __syncthreads();
#pragma unroll
    for (int r = 0; r < 4; ++r) {
        int d = d0 + ty + r * 8, n = n0 + tx;
        int8_t q = 0;
        if (n < NTOK) {
            float v = __fadd_rn(__fmul_rn(tile[tx][ty + r * 8], g_v1a[d]), nb1[d]);
            q = (int8_t)fqq(v, s0);
        }
        g_qa1t[((long)b * DIM + d) * KPAD + n] = q;
    }
}

// ---------------------------------------------------------------------------
// int8 tensor-core GEMM, cp.async double-buffered + ldmatrix fragments
// C[M,N] = A[M,K] (k-major) * B[N,K]^T (k-major)
// ---------------------------------------------------------------------------

__device__ __forceinline__ unsigned s2u(const void* p) {
    return (unsigned)__cvta_generic_to_shared(p);
}
__device__ __forceinline__ void cp16(void* d, const void* s) {
    asm volatile("cp.async.cg.shared.global [%0], [%1], 16;\n"
                 :: "r"(s2u(d)), "l"(s) : "memory");
}
__device__ __forceinline__ void cpcommit() {
    asm volatile("cp.async.commit_group;\n" ::: "memory");
}
template <int N> __device__ __forceinline__ void cpwait() {
    asm volatile("cp.async.wait_group %0;\n" :: "n"(N) : "memory");
}
__device__ __forceinline__ void ldsm4(unsigned& r0, unsigned& r1,
                                      unsigned& r2, unsigned& r3, const void* p) {
    asm volatile("ldmatrix.sync.aligned.m8n8.x4.shared.b16 {%0,%1,%2,%3}, [%4];\n"
                 : "=r"(r0), "=r"(r1), "=r"(r2), "=r"(r3) : "r"(s2u(p)));
}
__device__ __forceinline__ void mma_s8(int* c, const unsigned* a,
                                       unsigned b0, unsigned b1) {
    asm volatile(
        "mma.sync.aligned.m16n8k32.row.col.s32.s8.s8.s32 "
        "{%0,%1,%2,%3},{%4,%5,%6,%7},{%8,%9},{%0,%1,%2,%3};\n"
        : "+r"(c[0]), "+r"(c[1]), "+r"(c[2]), "+r"(c[3])
        : "r"(a[0]), "r"(a[1]), "r"(a[2]), "r"(a[3]), "r"(b0), "r"(b1));
}

constexpr int AST = 80;   // smem row stride (bytes): (20r+c) mod 32 is a perm

template <int STAGE>
__global__ void __launch_bounds__(256, 2)
gemm_s8_k(int M, int N, int K,
          const float* __restrict__ sc,
          const float* __restrict__ bias,
          const float* __restrict__ xorg,
          const float* __restrict__ nb2,
          float* __restrict__ outf) {

    __shared__ int8_t smA[2][128 * AST];
    __shared__ int8_t smB[2][128 * AST];

    const int tid  = threadIdx.x;
    const int warp = tid >> 5, lane = tid & 31;
    const int wm = warp >> 2, wn = warp & 3;
    const int m0 = blockIdx.y * 128;
    const int n0 = blockIdx.x * 128;
    const int bz = blockIdx.z;

    const int8_t* Ab;
    const int8_t* Bb;
    if (STAGE == 0)      { Ab = g_qWattn; Bb = g_qa1t + (long)bz * DIM * KPAD; }
    else if (STAGE == 1) { Ab = g_qa2;    Bb = g_qW1vt; }
    else if (STAGE == 2) { Ab = g_qa3;    Bb = g_qW1u; }
    else if (STAGE == 3) { Ab = g_qa4;    Bb = g_qW2vt; }
    else                 { Ab = g_qa5;    Bb = g_qW2u; }

    // loader mapping: two 16B chunks per thread per matrix per k-tile
    const int lr0 = tid >> 2,        lc0 = (tid & 3) << 4;
    const int lr1 = (tid + 256) >> 2, lc1 = lc0;   // same column, +64 rows

    auto load_stage = [&](int kt, int s) {
        long gk = (long)kt * 64;
        cp16(&smA[s][lr0 * AST + lc0], Ab + (long)(m0 + lr0) * K + gk + lc0);
        cp16(&smA[s][lr1 * AST + lc1], Ab + (long)(m0 + lr1) * K + gk + lc1);
        cp16(&smB[s][lr0 * AST + lc0], Bb + (long)(n0 + lr0) * K + gk + lc0);
        cp16(&smB[s][lr1 * AST + lc1], Bb + (long)(n0 + lr1) * K + gk + lc1);
        cpcommit();
    };

    int acc[4][4][4];
#pragma unroll
    for (int i = 0; i < 4; ++i)
#pragma unroll
        for (int j = 0; j < 4; ++j)
#pragma unroll
            for (int t = 0; t < 4; ++t) acc[i][j][t] = 0;

    const int ktiles = K >> 6;
    load_stage(0, 0);

    // precomputed smem addresses (lane-dependent parts)
    const int aRow = (lane & 15);
    const int aCol = ((lane >> 4) << 4);
    const int bRow = (lane & 7) + ((lane >> 4) << 3);
    const int bCol = (((lane >> 3) & 1) << 4);

    for (int kt = 0; kt < ktiles; ++kt) {
        cpwait<0>();
        __syncthreads();
        if (kt + 1 < ktiles) load_stage(kt + 1, (kt + 1) & 1);
        const int s = kt & 1;

#pragma unroll
        for (int ks = 0; ks < 2; ++ks) {
            unsigned a[4][4];
#pragma unroll
            for (int i = 0; i < 4; ++i) {
                const int8_t* p = &smA[s][(wm * 64 + i * 16 + aRow) * AST
                                          + aCol + ks * 32];
                ldsm4(a[i][0], a[i][1], a[i][2], a[i][3], p);
            }
#pragma unroll
            for (int jp = 0; jp < 2; ++jp) {
                unsigned b0, b1, b2, b3;
                const int8_t* q = &smB[s][(wn * 32 + jp * 16 + bRow) * AST
                                          + bCol + ks * 32];
                ldsm4(b0, b1, b2, b3, q);
#pragma unroll
                for (int i = 0; i < 4; ++i) {
                    mma_s8(acc[i][jp * 2 + 0], a[i], b0, b1);
                    mma_s8(acc[i][jp * 2 + 1], a[i], b2, b3);
                }
            }
        }
        __syncthreads();
    }

    // ---- epilogue ----
    const float sc1 = sc[1], sc2 = sc[2], sc3 = sc[3], sc4 = sc[4];
    const float sc5 = sc[5], sc6 = sc[6], sc7 = sc[7], sc8 = sc[8], sc9 = sc[9];
    float swp;
    if (STAGE == 0)      swp = sc[0] * wscale(0);
    else if (STAGE == 1) swp = sc2 * wscale(1);
    else if (STAGE == 2) swp = sc4 * wscale(2);
    else if (STAGE == 3) swp = sc6 * wscale(3);
    else                 swp = sc7 * wscale(4);

#pragma unroll
    for (int i = 0; i < 4; ++i) {
        int mrow = m0 + wm * 64 + i * 16 + (lane >> 2);
#pragma unroll
        for (int j = 0; j < 4; ++j) {
            int nn = n0 + wn * 32 + j * 8 + ((lane & 3) << 1);
#pragma unroll
            for (int h = 0; h < 2; ++h) {
                int mm = mrow + h * 8;
                if (mm >= M) continue;
                float a0 = (float)acc[i][j][h * 2 + 0];
                float a1 = (float)acc[i][j][h * 2 + 1];

                if (STAGE == 0) {
                    float bm = bias[mm];
                    float v0 = __fadd_rn(__fmul_rn(a0, swp), bm);
                    float v1 = __fadd_rn(__fmul_rn(a1, swp), bm);
                    float t0 = __fmul_rn(__fmul_rn(sc1, fqq(v0, sc1)), g_g1[nn]);
                    float t1 = __fmul_rn(__fmul_rn(sc1, fqq(v1, sc1)), g_g1[nn + 1]);
                    long idx = ((long)bz * NTOK + mm) * DIM + nn;
                    float2 xo = *(const float2*)(xorg + idx);
                    float q80 = fqq(__fadd_rn(t0, xo.x), sc8);
                    float q81 = fqq(__fadd_rn(t1, xo.y), sc8);
                    *(char2*)(g_qx1 + idx) = make_char2((int8_t)q80, (int8_t)q81);
                    float x10 = __fmul_rn(sc8, q80), x11 = __fmul_rn(sc8, q81);
                    float h0 = __fadd_rn(__fmul_rn(x10, g_v2a[nn]),     nb2[nn]);
                    float h1 = __fadd_rn(__fmul_rn(x11, g_v2a[nn + 1]), nb2[nn + 1]);
                    *(char2*)(g_qa2 + idx) =
                        make_char2((int8_t)fqq(h0, sc2), (int8_t)fqq(h1, sc2));
                } else if (STAGE == 1) {
                    float v0 = __fadd_rn(__fmul_rn(a0, swp), bias[nn]);
                    float v1 = __fadd_rn(__fmul_rn(a1, swp), bias[nn + 1]);
                    *(char2*)(g_qa3 + (long)mm * RNK + nn) =
                        make_char2((int8_t)fqq(v0, sc4), (int8_t)fqq(v1, sc4));
                } else if (STAGE == 2) {
                    float v0 = __fadd_rn(__fmul_rn(a0, swp), bias[nn]);
                    float v1 = __fadd_rn(__fmul_rn(a1, swp), bias[nn + 1]);
                    float t0 = __fmul_rn(sc5, fqq(v0, sc5));
                    float t1 = __fmul_rn(sc5, fqq(v1, sc5));
                    float g0 = __fmul_rn(__fmul_rn(0.5f, t0),
                               __fadd_rn(1.f, erff(__fmul_rn(t0, 0.70710678118654752f))));
                    float g1v = __fmul_rn(__fmul_rn(0.5f, t1),
                               __fadd_rn(1.f, erff(__fmul_rn(t1, 0.70710678118654752f))));
                    *(char2*)(g_qa4 + (long)mm * HID + nn) =
                        make_char2((int8_t)fqq(g0, sc6), (int8_t)fqq(g1v, sc6));
                } else if (STAGE == 3) {
                    float v0 = __fadd_rn(__fmul_rn(a0, swp), bias[nn]);
                    float v1 = __fadd_rn(__fmul_rn(a1, swp), bias[nn + 1]);
                    *(char2*)(g_qa5 + (long)mm * RNK + nn) =
                        make_char2((int8_t)fqq(v0, sc7), (int8_t)fqq(v1, sc7));
                } else {
                    float v0 = __fadd_rn(__fmul_rn(a0, swp), bias[nn]);
                    float v1 = __fadd_rn(__fmul_rn(a1, swp), bias[nn + 1]);
                    float t0 = __fmul_rn(__fmul_rn(sc3, fqq(v0, sc3)), g_g2[nn]);
                    float t1 = __fmul_rn(__fmul_rn(sc3, fqq(v1, sc3)), g_g2[nn + 1]);
                    long idx = (long)mm * DIM + nn;
                    char2 qx = *(const char2*)(g_qx1 + idx);
                    float r0 = __fadd_rn(t0, __fmul_rn(sc8, (float)qx.x));
                    float r1 = __fadd_rn(t1, __fmul_rn(sc8, (float)qx.y));
                    float2 o;
                    o.x = __fmul_rn(sc9, fqq(r0, sc9));
                    o.y = __fmul_rn(sc9, fqq(r1, sc9));
                    *(float2*)(outf + idx) = o;
                }
            }
        }
    }
}

} // anonymous namespace

// ---------------------------------------------------------------------------
extern "C" void kernel_launch(void* const* d_in, const int* in_sizes, int n_in,
                              void* d_out, int out_size) {
    const float* x    = (const float*)d_in[0];
    const float* n1a  = (const float*)d_in[1];
    const float* n1b  = (const float*)d_in[2];
    const float* attw = (const float*)d_in[3];
    const float* attb = (const float*)d_in[4];
    const float* g1   = (const float*)d_in[5];
    const float* n2a  = (const float*)d_in[6];
    const float* n2b  = (const float*)d_in[7];
    const float* w1vt = (const float*)d_in[8];
    const float* b1vt = (const float*)d_in[9];
    const float* w1u  = (const float*)d_in[10];
    const float* b1u  = (const float*)d_in[11];
    const float* w2vt = (const float*)d_in[12];
    const float* b2vt = (const float*)d_in[13];
    const float* w2u  = (const float*)d_in[14];
    const float* b2u  = (const float*)d_in[15];
    const float* g2   = (const float*)d_in[16];
    const float* sc   = (const float*)d_in[17];
    float* out = (float*)d_out;

    quant_vectors_k<<<4, 256>>>(n1a, n2a, g1, g2);               // + absmax reset
    absmax_all_k<<<dim3(96, 5), 256>>>(attw, w1vt, w1u, w2vt, w2u);
    quantw_all_k<<<dim3(128, 5), 256>>>(attw, w1vt, w1u, w2vt, w2u);

    {   // stage 0: norm1 + fq(s0), transpose to [b][d][npad], zero-pad n
        dim3 grid(DIM / 32, KPAD / 32, BATCH);
        dim3 blk(32, 8);
        stage0_k<<<grid, blk>>>(x, n1b, sc);
    }
    {   // attn token-mixing GEMM + fused residual / norm2 epilogue
        dim3 grid(DIM / 128, 2, BATCH);
        gemm_s8_k<0><<<grid, 256>>>(NTOK, DIM, KPAD, sc, attb, x, n2b, nullptr);
    }
    {   // fc1_vt
        dim3 grid(RNK / 128, (int)(TROWS / 128), 1);
        gemm_s8_k<1><<<grid, 256>>>((int)TROWS, RNK, DIM, sc, b1vt, x, n2b, nullptr);
    }
    {   // fc1_u + GELU
        dim3 grid(HID / 128, (int)(TROWS / 128), 1);
        gemm_s8_k<2><<<grid, 256>>>((int)TROWS, HID, RNK, sc, b1u, x, n2b, nullptr);
    }
    {   // fc2_vt
        dim3 grid(RNK / 128, (int)(TROWS / 128), 1);
        gemm_s8_k<3><<<grid, 256>>>((int)TROWS, RNK, HID, sc, b2vt, x, n2b, nullptr);
    }
    {   // fc2_u + gamma2 + residual -> out
        dim3 grid(DIM / 128, (int)(TROWS / 128), 1);
        gemm_s8_k<4><<<grid, 256>>>((int)TROWS, DIM, RNK, sc, b2u, x, n2b, out);
    }
}